// round 16
// baseline (speedup 1.0000x reference)
#include <cuda_runtime.h>
#include <cuda_fp16.h>
#include <cstdint>

// ---------------------------------------------------------------------------
// RPN head via mma.sync f16 (tcgen05 blocked: harness PTX arch lacks 'a').
// R16 = R15 (best: 549.1us) + fork-join stream overlap:
//   conv1/conv2 each split into 4 image-aligned batches of 256 CTAs;
//   conv2 batch i depends ONLY on conv1 batch i (3x3 halo never crosses
//   images) -> conv2 runs on a second stream gated by per-batch events,
//   backfilling conv1's underfull waves. Streams/events are created once in
//   a static constructor (host objects; no device allocations).
//   conv1: 3x3 512->256 + bias + relu   -> h1 (fp16, gmem)
//   conv2: 3x3 256->256 + bias + relu   -> smem -> fused heads GEMM
//          (M=64 N=64(54) K=256) + bias + pairwise softmax -> out
// ---------------------------------------------------------------------------

#define HDIM 128
#define WDIM 128
#define BATCH 4
#define COUT 256

__device__ __half g_x16[BATCH * HDIM * WDIM * 512];   // 64 MiB
__device__ __half g_h1 [BATCH * HDIM * WDIM * COUT];  // 32 MiB
__device__ __half g_w1t[COUT * 9 * 512];
__device__ __half g_w2t[COUT * 9 * 256];
__device__ __half g_wh [64 * 256];
__device__ float  g_bh [64];

// ---------------- mma.sync / ldmatrix / cp.async helpers -------------------

__device__ __forceinline__ void ldsm4(uint32_t* r, uint32_t addr) {
    asm volatile("ldmatrix.sync.aligned.m8n8.x4.shared.b16 {%0,%1,%2,%3}, [%4];"
                 : "=r"(r[0]), "=r"(r[1]), "=r"(r[2]), "=r"(r[3]) : "r"(addr));
}

__device__ __forceinline__ void mma16816(float* d, const uint32_t* a,
                                         const uint32_t* b) {
    asm volatile(
        "mma.sync.aligned.m16n8k16.row.col.f32.f16.f16.f32 "
        "{%0,%1,%2,%3}, {%4,%5,%6,%7}, {%8,%9}, {%0,%1,%2,%3};"
        : "+f"(d[0]), "+f"(d[1]), "+f"(d[2]), "+f"(d[3])
        : "r"(a[0]), "r"(a[1]), "r"(a[2]), "r"(a[3]), "r"(b[0]), "r"(b[1]));
}

__device__ __forceinline__ void cp_async16(uint32_t dst, const void* src,
                                           uint32_t nbytes) {
    asm volatile("cp.async.cg.shared.global [%0], [%1], 16, %2;"
                 :: "r"(dst), "l"(src), "r"(nbytes));
}
#define CP_COMMIT() asm volatile("cp.async.commit_group;")
#define CP_WAIT0()  asm volatile("cp.async.wait_group 0;")

// cp.async completion -> mbarrier arrive (noinc: init count covers it)
#define CPASYNC_MBAR_ARRIVE(addr) \
    asm volatile("cp.async.mbarrier.arrive.noinc.shared.b64 [%0];" \
                 :: "r"((uint32_t)(addr)) : "memory")

#define MBARRIER_INIT(mbar, count) \
    asm volatile("mbarrier.init.shared.b64 [%0], %1;" \
                 :: "r"((uint32_t)(mbar)), "r"((uint32_t)(count)) : "memory")

#define MBARRIER_ARRIVE(mbar) \
    asm volatile("mbarrier.arrive.shared.b64 _, [%0];" \
                 :: "r"((uint32_t)(mbar)) : "memory")

#define MBARRIER_WAIT_PARITY(mbar_smem_addr, phase_parity) do { \
    uint32_t _mbar = (uint32_t)(mbar_smem_addr); \
    uint32_t _parity = (uint32_t)(phase_parity); \
    uint32_t _done; \
    asm volatile( \
        "{\n\t.reg .pred p;\n\t" \
        "mbarrier.try_wait.parity.acquire.cta.shared::cta.b64 p, [%1], %2;\n\t" \
        "selp.b32 %0, 1, 0, p;\n\t}" \
        : "=r"(_done) : "r"(_mbar), "r"(_parity) : "memory"); \
    if (!_done) { \
        asm volatile( \
            "{\n\t.reg .pred P1;\n\t" \
            "WAIT_LOOP_%=:\n\t" \
            "mbarrier.try_wait.parity.acquire.cta.shared::cta.b64 P1, [%0], %1, 0x989680;\n\t" \
            "@P1 bra.uni WAIT_DONE_%=;\n\t" \
            "bra.uni WAIT_LOOP_%=;\n\t" \
            "WAIT_DONE_%=:\n\t}" \
            :: "r"(_mbar), "r"(_parity) : "memory"); \
    } \
} while(0)

// ---------------------------------------------------------------------------
// Fused prep kernel (R15): cvt + tiled W transposes + head pack
// ---------------------------------------------------------------------------
#define PREP_CVT_BLKS  8192
#define PREP_W1_BLKS   (144 * 8)
#define PREP_W2_BLKS   (72 * 8)
#define PREP_WH_BLKS   64
#define PREP_GRID (PREP_CVT_BLKS + PREP_W1_BLKS + PREP_W2_BLKS + PREP_WH_BLKS)

__device__ __forceinline__ void wtrans_tile(const float* __restrict__ w,
                                            __half* __restrict__ wt,
                                            int K, int tb, int tid,
                                            __half (*tile)[33])
{
    const int tk = tb >> 3;
    const int tn = tb & 7;
    const int r8  = tid >> 5;     // 0..7
    const int c32 = tid & 31;     // 0..31
#pragma unroll
    for (int i = 0; i < 4; ++i) {
        const int kl = i * 8 + r8;
        tile[c32][kl] = __float2half(
            w[(size_t)(tk * 32 + kl) * 256 + tn * 32 + c32]);
    }
    __syncthreads();
#pragma unroll
    for (int i = 0; i < 4; ++i) {
        const int nl = i * 8 + r8;
        wt[(size_t)(tn * 32 + nl) * K + tk * 32 + c32] = tile[nl][c32];
    }
}

__global__ void prep_kernel(const float* __restrict__ x,
                            const float* __restrict__ W1,
                            const float* __restrict__ W2,
                            const float* __restrict__ Wr,
                            const float* __restrict__ br,
                            const float* __restrict__ Wc,
                            const float* __restrict__ bc,
                            __half* __restrict__ x16,
                            __half* __restrict__ w1t,
                            __half* __restrict__ w2t,
                            __half* __restrict__ wh,
                            float* __restrict__ bh)
{
    __shared__ __half tile[32][33];
    const int bid = blockIdx.x;
    const int tid = threadIdx.x;
    if (bid < PREP_CVT_BLKS) {
        const size_t i0 = (size_t)bid * 512 + tid;
        const size_t i1 = i0 + 256;
        const float4* p0 = (const float4*)x + i0 * 2;
        const float4* p1 = (const float4*)x + i1 * 2;
        const float4 a0 = p0[0], b0 = p0[1];
        const float4 a1 = p1[0], b1 = p1[1];
        __half2 h0[4], h1[4];
        h0[0] = __floats2half2_rn(a0.x, a0.y);
        h0[1] = __floats2half2_rn(a0.z, a0.w);
        h0[2] = __floats2half2_rn(b0.x, b0.y);
        h0[3] = __floats2half2_rn(b0.z, b0.w);
        h1[0] = __floats2half2_rn(a1.x, a1.y);
        h1[1] = __floats2half2_rn(a1.z, a1.w);
        h1[2] = __floats2half2_rn(b1.x, b1.y);
        h1[3] = __floats2half2_rn(b1.z, b1.w);
        *(uint4*)(x16 + i0 * 8) = *(uint4*)h0;
        *(uint4*)(x16 + i1 * 8) = *(uint4*)h1;
    } else if (bid < PREP_CVT_BLKS + PREP_W1_BLKS) {
        wtrans_tile(W1, w1t, 4608, bid - PREP_CVT_BLKS, tid, tile);
    } else if (bid < PREP_CVT_BLKS + PREP_W1_BLKS + PREP_W2_BLKS) {
        wtrans_tile(W2, w2t, 2304, bid - PREP_CVT_BLKS - PREP_W1_BLKS,
                    tid, tile);
    } else {
        const int idx = (bid - PREP_CVT_BLKS - PREP_W1_BLKS - PREP_W2_BLKS)
                        * 256 + tid;
        const int n  = idx & 63;
        const int ci = idx >> 6;
        float v = 0.f;
        if (n < 54) {
            const int a = n / 6, j = n - 6 * a;
            v = (j < 2) ? Wc[ci * 18 + 2 * a + j]
                        : Wr[ci * 36 + 4 * a + (j - 2)];
        }
        wh[(size_t)n * 256 + ci] = __float2half(v);
        if (ci == 0) {
            float bb = 0.f;
            if (n < 54) {
                const int a = n / 6, j = n - 6 * a;
                bb = (j < 2) ? bc[2 * a + j] : br[4 * a + (j - 2)];
            }
            bh[n] = bb;
        }
    }
}

// ---------------------------------------------------------------------------
// Implicit-GEMM 3x3 SAME conv + bias + relu on mma.sync f16.
// BM=64, BN=256, BK=32, 5-buffer mbarrier pipeline (3-ahead), 8 warps,
// 2 CTAs/SM, x5-unrolled mainloop. tile0 = batch tile offset.
// FUSE=true runs the heads GEMM from an smem-held h2 tile.
// ---------------------------------------------------------------------------
template <int CIN, bool FUSE>
__global__ __launch_bounds__(256, 2)
void conv_mma(const __half* __restrict__ in, const __half* __restrict__ wt,
              const float* __restrict__ bias, void* __restrict__ outv,
              const __half* __restrict__ wh, const float* __restrict__ bh,
              int tile0)
{
    constexpr int KTOT = 9 * CIN;
    constexpr int BK = 32;
    constexpr int NS = KTOT / BK;          // 144 or 72
    constexpr int NBUF = 5;
    constexpr int STGB = 20480;            // A 4KB + B 16KB per stage
    constexpr int HROW = 528;              // fused tile row stride (bytes)

    extern __shared__ char smem[];
    const uint32_t sb = (uint32_t)__cvta_generic_to_shared(smem);
    float* bias_s = (float*)(smem + NBUF * STGB);
    float* bh_s   = bias_s + 256;
    const uint32_t mb_full  = sb + NBUF * STGB + 1280;   // 5 x 8B
    const uint32_t mb_empty = mb_full + 40;              // 5 x 8B

    const int tid = threadIdx.x;
    const int lid = tid & 31;
    const int wid = tid >> 5;
    const int wm = wid & 1;                // 2 M groups of 32 rows
    const int wn = wid >> 1;               // 4 N groups of 64 cols

    const int tileg = tile0 + blockIdx.x;
    const int bm = tileg >> 1;             // row index: b*128 + y
    const int x0 = (tileg & 1) * 64;       // half-row offset
    const int b  = bm >> 7;
    const int y  = bm & 127;
    const __half* inb = in + (size_t)b * HDIM * WDIM * CIN;

    bias_s[tid] = bias[tid];
    if (FUSE && tid < 64) bh_s[tid] = bh[tid];
    if (tid == 0) {
#pragma unroll
        for (int i = 0; i < NBUF; ++i) {
            MBARRIER_INIT(mb_full  + 8 * i, 256);
            MBARRIER_INIT(mb_empty + 8 * i, 8);
        }
    }
    __syncthreads();

    const int sh = tid & 3;                // k-half within BK (16B)
    const int sm = tid >> 2;               // row 0..63

    auto issue = [&](int s, int buf) {
        const int k0  = s * BK;
        const int tap = k0 / CIN;
        const int ci0 = k0 - tap * CIN;
        const int ky  = tap / 3;
        const int kx  = tap - 3 * ky;
        const int yin = y + ky - 1;
        const bool yok = (unsigned)yin < (unsigned)HDIM;
        const uint32_t ab  = sb + (uint32_t)buf * STGB;
        const uint32_t bb2 = ab + 4096;
        {   // A: one 16B unit per thread
            const int xin = x0 + sm + kx - 1;
            const bool ok = yok && ((unsigned)xin < (unsigned)WDIM);
            const __half* src = ok
                ? inb + ((size_t)(yin * WDIM + xin) * CIN + ci0 + sh * 8)
                : inb;
            const uint32_t unit = sm * 4 + (sh ^ ((sm >> 1) & 3));
            cp_async16(ab + unit * 16, src, ok ? 16u : 0u);
        }
#pragma unroll
        for (int i = 0; i < 4; ++i) {      // B: 256 n-rows
            const int n = sm + 64 * i;
            const __half* src = wt + (size_t)n * KTOT + k0 + sh * 8;
            const uint32_t unit = n * 4 + (sh ^ ((n >> 1) & 3));
            cp_async16(bb2 + unit * 16, src, 16u);
        }
    };

    const int q = lid >> 3;
    const int r = lid & 7;

    uint32_t offA[2][2], offB[2][4];
#pragma unroll
    for (int c = 0; c < 2; ++c) {
#pragma unroll
        for (int i = 0; i < 2; ++i) {
            const int m = wm * 32 + i * 16 + (q & 1) * 8 + r;
            const int h = 2 * c + (q >> 1);
            offA[c][i] = (m * 4 + (h ^ ((m >> 1) & 3))) * 16;
        }
#pragma unroll
        for (int p = 0; p < 4; ++p) {
            const int n = wn * 64 + p * 16 + (q >> 1) * 8 + r;
            const int h = 2 * c + (q & 1);
            offB[c][p] = (n * 4 + (h ^ ((n >> 1) & 3))) * 16 + 4096;
        }
    }

    float acc[2][8][4];
#pragma unroll
    for (int i = 0; i < 2; ++i)
#pragma unroll
        for (int j = 0; j < 8; ++j)
#pragma unroll
            for (int k = 0; k < 4; ++k) acc[i][j][k] = 0.0f;

    // ---- prologue: 3 stages in flight ----
#pragma unroll
    for (int t = 0; t < 3; ++t) {
        issue(t, t);
        CPASYNC_MBAR_ARRIVE(mb_full + 8 * t);
    }

    int cb = 0, cph = 0;                   // consumer buffer / parity
    int pb = 3, pph = 0;                   // producer buffer / parity

#pragma unroll 5
    for (int s = 0; s < NS; ++s) {
        MBARRIER_WAIT_PARITY(mb_full + 8 * cb, cph);

        // producer: stage s+3 cp.asyncs enter the pipe early
        const int t = s + 3;
        if (t < NS) {
            if (t >= NBUF) MBARRIER_WAIT_PARITY(mb_empty + 8 * pb, pph);
            issue(t, pb);
            CPASYNC_MBAR_ARRIVE(mb_full + 8 * pb);
            if (++pb == NBUF) { pb = 0; if (t >= NBUF) pph ^= 1; }
        }

        const uint32_t ab = sb + (uint32_t)cb * STGB;
        uint32_t af[2][4], bf[4][4];
#pragma unroll
        for (int i = 0; i < 2; ++i) ldsm4(af[i], ab + offA[0][i]);
#pragma unroll
        for (int p = 0; p < 4; ++p) ldsm4(bf[p], ab + offB[0][p]);

#pragma unroll
        for (int i = 0; i < 2; ++i)
#pragma unroll
            for (int j = 0; j < 8; ++j)
                mma16816(acc[i][j], af[i], &bf[j >> 1][(j & 1) * 2]);

#pragma unroll
        for (int i = 0; i < 2; ++i) ldsm4(af[i], ab + offA[1][i]);
#pragma unroll
        for (int p = 0; p < 4; ++p) ldsm4(bf[p], ab + offB[1][p]);

        // ldmatrix.sync is warp-collective: all lanes' reads done here
        if (lid == 0) MBARRIER_ARRIVE(mb_empty + 8 * cb);

#pragma unroll
        for (int i = 0; i < 2; ++i)
#pragma unroll
            for (int j = 0; j < 8; ++j)
                mma16816(acc[i][j], af[i], &bf[j >> 1][(j & 1) * 2]);

        if (++cb == NBUF) { cb = 0; cph ^= 1; }
    }

    const int g  = lid >> 2;
    const int t4 = lid & 3;
    const size_t posb = (size_t)bm * 128 + x0;

    if constexpr (!FUSE) {
        // -------- epilogue: bias + relu + fp16 store to gmem --------
        __half* out = (__half*)outv;
#pragma unroll
        for (int i = 0; i < 2; ++i) {
#pragma unroll
            for (int row = 0; row < 2; ++row) {
                const int m = wm * 32 + i * 16 + row * 8 + g;
                __half* op = out + (posb + m) * COUT;
#pragma unroll
                for (int j = 0; j < 8; ++j) {
                    const int n = wn * 64 + j * 8 + 2 * t4;
                    const float v0 = fmaxf(acc[i][j][row * 2 + 0] + bias_s[n], 0.f);
                    const float v1 = fmaxf(acc[i][j][row * 2 + 1] + bias_s[n + 1], 0.f);
                    *(__half2*)(op + n) = __floats2half2_rn(v0, v1);
                }
            }
        }
    } else {
        // -------- fused heads: h2 tile -> smem, heads GEMM, softmax --------
        float* out = (float*)outv;
        const uint32_t h2b = sb;                 // overlays bufs 0..1
        const uint32_t whb = sb + 2 * STGB;      // overlays bufs 2..3

        __syncthreads();   // all warps done reading pipeline bufs

        {   // stage Wh[64][256]: 4 threads/row, 8 units each
            const int n4 = tid >> 2;
            const int h4 = tid & 3;
#pragma unroll
            for (int i = 0; i < 8; ++i) {
                const int h = h4 * 8 + i;       // unit 0..31
                cp_async16(whb + (uint32_t)(n4 * HROW + h * 16),
                           wh + (size_t)n4 * 256 + h * 8, 16u);
            }
        }
        CP_COMMIT();

        // write h2 tile (relu + bias, fp16)
#pragma unroll
        for (int i = 0; i < 2; ++i) {
#pragma unroll
            for (int row = 0; row < 2; ++row) {
                const int m = wm * 32 + i * 16 + row * 8 + g;
#pragma unroll
                for (int j = 0; j < 8; ++j) {
                    const int n = wn * 64 + j * 8 + 2 * t4;
                    const float v0 = fmaxf(acc[i][j][row * 2 + 0] + bias_s[n], 0.f);
                    const float v1 = fmaxf(acc[i][j][row * 2 + 1] + bias_s[n + 1], 0.f);
                    const __half2 hv = __floats2half2_rn(v0, v1);
                    const uint32_t addr = h2b + (uint32_t)(m * HROW + (n >> 3) * 16
                                                           + (n & 7) * 2);
                    asm volatile("st.shared.b32 [%0], %1;"
                                 :: "r"(addr), "r"(*(const uint32_t*)&hv)
                                 : "memory");
                }
            }
        }
        CP_WAIT0();
        __syncthreads();

        // heads GEMM: 64x64x256, warp tile 32(m) x 16(n)
        const int wm2 = wid & 1;
        const int wn2 = wid >> 1;
        float acc2[2][2][4];
#pragma unroll
        for (int i = 0; i < 2; ++i)
#pragma unroll
            for (int j = 0; j < 2; ++j)
#pragma unroll
                for (int k = 0; k < 4; ++k) acc2[i][j][k] = 0.0f;

        uint32_t hoffA[2], hoffB;
#pragma unroll
        for (int i = 0; i < 2; ++i) {
            const int m = wm2 * 32 + i * 16 + (q & 1) * 8 + r;
            hoffA[i] = (uint32_t)(m * HROW + (q >> 1) * 16);
        }
        {
            const int n = wn2 * 16 + (q >> 1) * 8 + r;
            hoffB = (uint32_t)(n * HROW + (q & 1) * 16);
        }

#pragma unroll
        for (int c = 0; c < 16; ++c) {          // 16 k16 chunks
            const uint32_t koff = (uint32_t)(c * 32);
            uint32_t af2[2][4], bf2[4];
#pragma unroll
            for (int i = 0; i < 2; ++i)
                ldsm4(af2[i], h2b + hoffA[i] + koff);
            ldsm4(bf2, whb + hoffB + koff);
#pragma unroll
            for (int i = 0; i < 2; ++i)
#pragma unroll
                for (int j = 0; j < 2; ++j)
                    mma16816(acc2[i][j], af2[i], &bf2[j * 2]);
        }

        // epilogue: bias + pairwise softmax + store
#pragma unroll
        for (int i = 0; i < 2; ++i) {
#pragma unroll
            for (int row = 0; row < 2; ++row) {
                const int m = wm2 * 32 + i * 16 + row * 8 + g;
                float* op = out + (posb + m) * 54;
#pragma unroll
                for (int j = 0; j < 2; ++j) {
                    const int n0 = wn2 * 16 + j * 8 + 2 * t4;
                    if (n0 < 54) {
                        float v0 = acc2[i][j][row * 2 + 0] + bh_s[n0];
                        float v1 = acc2[i][j][row * 2 + 1] + bh_s[n0 + 1];
                        const int a   = n0 / 6;
                        const int rem = n0 - 6 * a;
                        if (rem == 0) {
                            const float mx = fmaxf(v0, v1);
                            const float e0 = __expf(v0 - mx);
                            const float e1 = __expf(v1 - mx);
                            const float inv = 1.0f / (e0 + e1);
                            v0 = e0 * inv;
                            v1 = e1 * inv;
                        }
                        *(float2*)(op + n0) = make_float2(v0, v1);
                    }
                }
            }
        }
    }
}

// ---------------------------------------------------------------------------
// Static stream/event resources (host objects; created once at load).
// ---------------------------------------------------------------------------
namespace {
struct OverlapRes {
    cudaStream_t s2 = nullptr;
    cudaEvent_t  ev[4] = {};
    cudaEvent_t  efin = nullptr;
    OverlapRes() {
        cudaStreamCreateWithFlags(&s2, cudaStreamNonBlocking);
        for (int i = 0; i < 4; ++i)
            cudaEventCreateWithFlags(&ev[i], cudaEventDisableTiming);
        cudaEventCreateWithFlags(&efin, cudaEventDisableTiming);
    }
};
OverlapRes g_ov;
}

// ---------------------------------------------------------------------------
extern "C" void kernel_launch(void* const* d_in, const int* in_sizes, int n_in,
                              void* d_out, int out_size)
{
    const float* x  = (const float*)d_in[0];
    const float* W1 = (const float*)d_in[1];
    const float* b1 = (const float*)d_in[2];
    const float* W2 = (const float*)d_in[3];
    const float* b2 = (const float*)d_in[4];
    const float* Wr = (const float*)d_in[5];
    const float* br = (const float*)d_in[6];
    const float* Wc = (const float*)d_in[7];
    const float* bc = (const float*)d_in[8];
    float* out = (float*)d_out;

    __half *x16p, *h1p, *w1tp, *w2tp, *whp;
    float *bhp;
    cudaGetSymbolAddress((void**)&x16p, g_x16);
    cudaGetSymbolAddress((void**)&h1p,  g_h1);
    cudaGetSymbolAddress((void**)&w1tp, g_w1t);
    cudaGetSymbolAddress((void**)&w2tp, g_w2t);
    cudaGetSymbolAddress((void**)&whp,  g_wh);
    cudaGetSymbolAddress((void**)&bhp,  g_bh);

    const int conv_smem = 5 * 20480 + 1536;   // 103936 B (2 CTAs/SM)
    cudaFuncSetAttribute(conv_mma<512, false>,
                         cudaFuncAttributeMaxDynamicSharedMemorySize, conv_smem);
    cudaFuncSetAttribute(conv_mma<256, true>,
                         cudaFuncAttributeMaxDynamicSharedMemorySize, conv_smem);

    prep_kernel<<<PREP_GRID, 256>>>(x, W1, W2, Wr, br, Wc, bc,
                                    x16p, w1tp, w2tp, whp, bhp);

    // conv1 image-aligned batches on the main stream; event after each.
    for (int i = 0; i < 4; ++i) {
        conv_mma<512, false><<<256, 256, conv_smem>>>(
            x16p, w1tp, b1, h1p, nullptr, bhp, i * 256);
        cudaEventRecord(g_ov.ev[i], 0);
    }
    // conv2 batch i depends only on conv1 batch i (halo stays inside image).
    for (int i = 0; i < 4; ++i) {
        cudaStreamWaitEvent(g_ov.s2, g_ov.ev[i], 0);
        conv_mma<256, true><<<256, 256, conv_smem, g_ov.s2>>>(
            h1p, w2tp, b2, out, whp, bhp, i * 256);
    }
    cudaEventRecord(g_ov.efin, g_ov.s2);
    cudaStreamWaitEvent(0, g_ov.efin, 0);
}

// round 17
// speedup vs baseline: 1.0699x; 1.0699x over previous
#include <cuda_runtime.h>
#include <cuda_fp16.h>
#include <cstdint>

// ---------------------------------------------------------------------------
// RPN head via mma.sync f16 (tcgen05 blocked: harness PTX arch lacks 'a').
// R17 = R15 kernels + two-stream PAIR fork-join:
//   batch = 2 images (512 tiles > 296 resident slots, so no occupancy loss).
//   main stream: c1b0 -> c2b0   (stream order = the exact data dependency)
//   stream B   : c1b1 -> c2b1
//   The two conv1 halves run CONCURRENTLY (independent tiles); each conv2
//   half backfills as soon as its own conv1 half drains. R16's mistake
//   (sequential same-stream batches) is avoided.
//   conv1: 3x3 512->256 + bias + relu   -> h1 (fp16, gmem)
//   conv2: 3x3 256->256 + bias + relu   -> smem -> fused heads GEMM
//          (M=64 N=64(54) K=256) + bias + pairwise softmax -> out
// ---------------------------------------------------------------------------

#define HDIM 128
#define WDIM 128
#define BATCH 4
#define COUT 256

__device__ __half g_x16[BATCH * HDIM * WDIM * 512];   // 64 MiB
__device__ __half g_h1 [BATCH * HDIM * WDIM * COUT];  // 32 MiB
__device__ __half g_w1t[COUT * 9 * 512];
__device__ __half g_w2t[COUT * 9 * 256];
__device__ __half g_wh [64 * 256];
__device__ float  g_bh [64];

// ---------------- mma.sync / ldmatrix / cp.async helpers -------------------

__device__ __forceinline__ void ldsm4(uint32_t* r, uint32_t addr) {
    asm volatile("ldmatrix.sync.aligned.m8n8.x4.shared.b16 {%0,%1,%2,%3}, [%4];"
                 : "=r"(r[0]), "=r"(r[1]), "=r"(r[2]), "=r"(r[3]) : "r"(addr));
}

__device__ __forceinline__ void mma16816(float* d, const uint32_t* a,
                                         const uint32_t* b) {
    asm volatile(
        "mma.sync.aligned.m16n8k16.row.col.f32.f16.f16.f32 "
        "{%0,%1,%2,%3}, {%4,%5,%6,%7}, {%8,%9}, {%0,%1,%2,%3};"
        : "+f"(d[0]), "+f"(d[1]), "+f"(d[2]), "+f"(d[3])
        : "r"(a[0]), "r"(a[1]), "r"(a[2]), "r"(a[3]), "r"(b[0]), "r"(b[1]));
}

__device__ __forceinline__ void cp_async16(uint32_t dst, const void* src,
                                           uint32_t nbytes) {
    asm volatile("cp.async.cg.shared.global [%0], [%1], 16, %2;"
                 :: "r"(dst), "l"(src), "r"(nbytes));
}
#define CP_COMMIT() asm volatile("cp.async.commit_group;")
#define CP_WAIT0()  asm volatile("cp.async.wait_group 0;")

// cp.async completion -> mbarrier arrive (noinc: init count covers it)
#define CPASYNC_MBAR_ARRIVE(addr) \
    asm volatile("cp.async.mbarrier.arrive.noinc.shared.b64 [%0];" \
                 :: "r"((uint32_t)(addr)) : "memory")

#define MBARRIER_INIT(mbar, count) \
    asm volatile("mbarrier.init.shared.b64 [%0], %1;" \
                 :: "r"((uint32_t)(mbar)), "r"((uint32_t)(count)) : "memory")

#define MBARRIER_ARRIVE(mbar) \
    asm volatile("mbarrier.arrive.shared.b64 _, [%0];" \
                 :: "r"((uint32_t)(mbar)) : "memory")

#define MBARRIER_WAIT_PARITY(mbar_smem_addr, phase_parity) do { \
    uint32_t _mbar = (uint32_t)(mbar_smem_addr); \
    uint32_t _parity = (uint32_t)(phase_parity); \
    uint32_t _done; \
    asm volatile( \
        "{\n\t.reg .pred p;\n\t" \
        "mbarrier.try_wait.parity.acquire.cta.shared::cta.b64 p, [%1], %2;\n\t" \
        "selp.b32 %0, 1, 0, p;\n\t}" \
        : "=r"(_done) : "r"(_mbar), "r"(_parity) : "memory"); \
    if (!_done) { \
        asm volatile( \
            "{\n\t.reg .pred P1;\n\t" \
            "WAIT_LOOP_%=:\n\t" \
            "mbarrier.try_wait.parity.acquire.cta.shared::cta.b64 P1, [%0], %1, 0x989680;\n\t" \
            "@P1 bra.uni WAIT_DONE_%=;\n\t" \
            "bra.uni WAIT_LOOP_%=;\n\t" \
            "WAIT_DONE_%=:\n\t}" \
            :: "r"(_mbar), "r"(_parity) : "memory"); \
    } \
} while(0)

// ---------------------------------------------------------------------------
// Fused prep kernel (R15): cvt + tiled W transposes + head pack
// ---------------------------------------------------------------------------
#define PREP_CVT_BLKS  8192
#define PREP_W1_BLKS   (144 * 8)
#define PREP_W2_BLKS   (72 * 8)
#define PREP_WH_BLKS   64
#define PREP_GRID (PREP_CVT_BLKS + PREP_W1_BLKS + PREP_W2_BLKS + PREP_WH_BLKS)

__device__ __forceinline__ void wtrans_tile(const float* __restrict__ w,
                                            __half* __restrict__ wt,
                                            int K, int tb, int tid,
                                            __half (*tile)[33])
{
    const int tk = tb >> 3;
    const int tn = tb & 7;
    const int r8  = tid >> 5;     // 0..7
    const int c32 = tid & 31;     // 0..31
#pragma unroll
    for (int i = 0; i < 4; ++i) {
        const int kl = i * 8 + r8;
        tile[c32][kl] = __float2half(
            w[(size_t)(tk * 32 + kl) * 256 + tn * 32 + c32]);
    }
    __syncthreads();
#pragma unroll
    for (int i = 0; i < 4; ++i) {
        const int nl = i * 8 + r8;
        wt[(size_t)(tn * 32 + nl) * K + tk * 32 + c32] = tile[nl][c32];
    }
}

__global__ void prep_kernel(const float* __restrict__ x,
                            const float* __restrict__ W1,
                            const float* __restrict__ W2,
                            const float* __restrict__ Wr,
                            const float* __restrict__ br,
                            const float* __restrict__ Wc,
                            const float* __restrict__ bc,
                            __half* __restrict__ x16,
                            __half* __restrict__ w1t,
                            __half* __restrict__ w2t,
                            __half* __restrict__ wh,
                            float* __restrict__ bh)
{
    __shared__ __half tile[32][33];
    const int bid = blockIdx.x;
    const int tid = threadIdx.x;
    if (bid < PREP_CVT_BLKS) {
        const size_t i0 = (size_t)bid * 512 + tid;
        const size_t i1 = i0 + 256;
        const float4* p0 = (const float4*)x + i0 * 2;
        const float4* p1 = (const float4*)x + i1 * 2;
        const float4 a0 = p0[0], b0 = p0[1];
        const float4 a1 = p1[0], b1 = p1[1];
        __half2 h0[4], h1[4];
        h0[0] = __floats2half2_rn(a0.x, a0.y);
        h0[1] = __floats2half2_rn(a0.z, a0.w);
        h0[2] = __floats2half2_rn(b0.x, b0.y);
        h0[3] = __floats2half2_rn(b0.z, b0.w);
        h1[0] = __floats2half2_rn(a1.x, a1.y);
        h1[1] = __floats2half2_rn(a1.z, a1.w);
        h1[2] = __floats2half2_rn(b1.x, b1.y);
        h1[3] = __floats2half2_rn(b1.z, b1.w);
        *(uint4*)(x16 + i0 * 8) = *(uint4*)h0;
        *(uint4*)(x16 + i1 * 8) = *(uint4*)h1;
    } else if (bid < PREP_CVT_BLKS + PREP_W1_BLKS) {
        wtrans_tile(W1, w1t, 4608, bid - PREP_CVT_BLKS, tid, tile);
    } else if (bid < PREP_CVT_BLKS + PREP_W1_BLKS + PREP_W2_BLKS) {
        wtrans_tile(W2, w2t, 2304, bid - PREP_CVT_BLKS - PREP_W1_BLKS,
                    tid, tile);
    } else {
        const int idx = (bid - PREP_CVT_BLKS - PREP_W1_BLKS - PREP_W2_BLKS)
                        * 256 + tid;
        const int n  = idx & 63;
        const int ci = idx >> 6;
        float v = 0.f;
        if (n < 54) {
            const int a = n / 6, j = n - 6 * a;
            v = (j < 2) ? Wc[ci * 18 + 2 * a + j]
                        : Wr[ci * 36 + 4 * a + (j - 2)];
        }
        wh[(size_t)n * 256 + ci] = __float2half(v);
        if (ci == 0) {
            float bb = 0.f;
            if (n < 54) {
                const int a = n / 6, j = n - 6 * a;
                bb = (j < 2) ? bc[2 * a + j] : br[4 * a + (j - 2)];
            }
            bh[n] = bb;
        }
    }
}

// ---------------------------------------------------------------------------
// Implicit-GEMM 3x3 SAME conv + bias + relu on mma.sync f16.
// BM=64, BN=256, BK=32, 5-buffer mbarrier pipeline (3-ahead), 8 warps,
// 2 CTAs/SM, x5-unrolled mainloop. tile0 = batch tile offset.
// FUSE=true runs the heads GEMM from an smem-held h2 tile.
// ---------------------------------------------------------------------------
template <int CIN, bool FUSE>
__global__ __launch_bounds__(256, 2)
void conv_mma(const __half* __restrict__ in, const __half* __restrict__ wt,
              const float* __restrict__ bias, void* __restrict__ outv,
              const __half* __restrict__ wh, const float* __restrict__ bh,
              int tile0)
{
    constexpr int KTOT = 9 * CIN;
    constexpr int BK = 32;
    constexpr int NS = KTOT / BK;          // 144 or 72
    constexpr int NBUF = 5;
    constexpr int STGB = 20480;            // A 4KB + B 16KB per stage
    constexpr int HROW = 528;              // fused tile row stride (bytes)

    extern __shared__ char smem[];
    const uint32_t sb = (uint32_t)__cvta_generic_to_shared(smem);
    float* bias_s = (float*)(smem + NBUF * STGB);
    float* bh_s   = bias_s + 256;
    const uint32_t mb_full  = sb + NBUF * STGB + 1280;   // 5 x 8B
    const uint32_t mb_empty = mb_full + 40;              // 5 x 8B

    const int tid = threadIdx.x;
    const int lid = tid & 31;
    const int wid = tid >> 5;
    const int wm = wid & 1;                // 2 M groups of 32 rows
    const int wn = wid >> 1;               // 4 N groups of 64 cols

    const int tileg = tile0 + blockIdx.x;
    const int bm = tileg >> 1;             // row index: b*128 + y
    const int x0 = (tileg & 1) * 64;       // half-row offset
    const int b  = bm >> 7;
    const int y  = bm & 127;
    const __half* inb = in + (size_t)b * HDIM * WDIM * CIN;

    bias_s[tid] = bias[tid];
    if (FUSE && tid < 64) bh_s[tid] = bh[tid];
    if (tid == 0) {
#pragma unroll
        for (int i = 0; i < NBUF; ++i) {
            MBARRIER_INIT(mb_full  + 8 * i, 256);
            MBARRIER_INIT(mb_empty + 8 * i, 8);
        }
    }
    __syncthreads();

    const int sh = tid & 3;                // k-half within BK (16B)
    const int sm = tid >> 2;               // row 0..63

    auto issue = [&](int s, int buf) {
        const int k0  = s * BK;
        const int tap = k0 / CIN;
        const int ci0 = k0 - tap * CIN;
        const int ky  = tap / 3;
        const int kx  = tap - 3 * ky;
        const int yin = y + ky - 1;
        const bool yok = (unsigned)yin < (unsigned)HDIM;
        const uint32_t ab  = sb + (uint32_t)buf * STGB;
        const uint32_t bb2 = ab + 4096;
        {   // A: one 16B unit per thread
            const int xin = x0 + sm + kx - 1;
            const bool ok = yok && ((unsigned)xin < (unsigned)WDIM);
            const __half* src = ok
                ? inb + ((size_t)(yin * WDIM + xin) * CIN + ci0 + sh * 8)
                : inb;
            const uint32_t unit = sm * 4 + (sh ^ ((sm >> 1) & 3));
            cp_async16(ab + unit * 16, src, ok ? 16u : 0u);
        }
#pragma unroll
        for (int i = 0; i < 4; ++i) {      // B: 256 n-rows
            const int n = sm + 64 * i;
            const __half* src = wt + (size_t)n * KTOT + k0 + sh * 8;
            const uint32_t unit = n * 4 + (sh ^ ((n >> 1) & 3));
            cp_async16(bb2 + unit * 16, src, 16u);
        }
    };

    const int q = lid >> 3;
    const int r = lid & 7;

    uint32_t offA[2][2], offB[2][4];
#pragma unroll
    for (int c = 0; c < 2; ++c) {
#pragma unroll
        for (int i = 0; i < 2; ++i) {
            const int m = wm * 32 + i * 16 + (q & 1) * 8 + r;
            const int h = 2 * c + (q >> 1);
            offA[c][i] = (m * 4 + (h ^ ((m >> 1) & 3))) * 16;
        }
#pragma unroll
        for (int p = 0; p < 4; ++p) {
            const int n = wn * 64 + p * 16 + (q >> 1) * 8 + r;
            const int h = 2 * c + (q & 1);
            offB[c][p] = (n * 4 + (h ^ ((n >> 1) & 3))) * 16 + 4096;
        }
    }

    float acc[2][8][4];
#pragma unroll
    for (int i = 0; i < 2; ++i)
#pragma unroll
        for (int j = 0; j < 8; ++j)
#pragma unroll
            for (int k = 0; k < 4; ++k) acc[i][j][k] = 0.0f;

    // ---- prologue: 3 stages in flight ----
#pragma unroll
    for (int t = 0; t < 3; ++t) {
        issue(t, t);
        CPASYNC_MBAR_ARRIVE(mb_full + 8 * t);
    }

    int cb = 0, cph = 0;                   // consumer buffer / parity
    int pb = 3, pph = 0;                   // producer buffer / parity

#pragma unroll 5
    for (int s = 0; s < NS; ++s) {
        MBARRIER_WAIT_PARITY(mb_full + 8 * cb, cph);

        // producer: stage s+3 cp.asyncs enter the pipe early
        const int t = s + 3;
        if (t < NS) {
            if (t >= NBUF) MBARRIER_WAIT_PARITY(mb_empty + 8 * pb, pph);
            issue(t, pb);
            CPASYNC_MBAR_ARRIVE(mb_full + 8 * pb);
            if (++pb == NBUF) { pb = 0; if (t >= NBUF) pph ^= 1; }
        }

        const uint32_t ab = sb + (uint32_t)cb * STGB;
        uint32_t af[2][4], bf[4][4];
#pragma unroll
        for (int i = 0; i < 2; ++i) ldsm4(af[i], ab + offA[0][i]);
#pragma unroll
        for (int p = 0; p < 4; ++p) ldsm4(bf[p], ab + offB[0][p]);

#pragma unroll
        for (int i = 0; i < 2; ++i)
#pragma unroll
            for (int j = 0; j < 8; ++j)
                mma16816(acc[i][j], af[i], &bf[j >> 1][(j & 1) * 2]);

#pragma unroll
        for (int i = 0; i < 2; ++i) ldsm4(af[i], ab + offA[1][i]);
#pragma unroll
        for (int p = 0; p < 4; ++p) ldsm4(bf[p], ab + offB[1][p]);

        // ldmatrix.sync is warp-collective: all lanes' reads done here
        if (lid == 0) MBARRIER_ARRIVE(mb_empty + 8 * cb);

#pragma unroll
        for (int i = 0; i < 2; ++i)
#pragma unroll
            for (int j = 0; j < 8; ++j)
                mma16816(acc[i][j], af[i], &bf[j >> 1][(j & 1) * 2]);

        if (++cb == NBUF) { cb = 0; cph ^= 1; }
    }

    const int g  = lid >> 2;
    const int t4 = lid & 3;
    const size_t posb = (size_t)bm * 128 + x0;

    if constexpr (!FUSE) {
        // -------- epilogue: bias + relu + fp16 store to gmem --------
        __half* out = (__half*)outv;
#pragma unroll
        for (int i = 0; i < 2; ++i) {
#pragma unroll
            for (int row = 0; row < 2; ++row) {
                const int m = wm * 32 + i * 16 + row * 8 + g;
                __half* op = out + (posb + m) * COUT;
#pragma unroll
                for (int j = 0; j < 8; ++j) {
                    const int n = wn * 64 + j * 8 + 2 * t4;
                    const float v0 = fmaxf(acc[i][j][row * 2 + 0] + bias_s[n], 0.f);
                    const float v1 = fmaxf(acc[i][j][row * 2 + 1] + bias_s[n + 1], 0.f);
                    *(__half2*)(op + n) = __floats2half2_rn(v0, v1);
                }
            }
        }
    } else {
        // -------- fused heads: h2 tile -> smem, heads GEMM, softmax --------
        float* out = (float*)outv;
        const uint32_t h2b = sb;                 // overlays bufs 0..1
        const uint32_t whb = sb + 2 * STGB;      // overlays bufs 2..3

        __syncthreads();   // all warps done reading pipeline bufs

        {   // stage Wh[64][256]: 4 threads/row, 8 units each
            const int n4 = tid >> 2;
            const int h4 = tid & 3;
#pragma unroll
            for (int i = 0; i < 8; ++i) {
                const int h = h4 * 8 + i;       // unit 0..31
                cp_async16(whb + (uint32_t)(n4 * HROW + h * 16),
                           wh + (size_t)n4 * 256 + h * 8, 16u);
            }
        }
        CP_COMMIT();

        // write h2 tile (relu + bias, fp16)
#pragma unroll
        for (int i = 0; i < 2; ++i) {
#pragma unroll
            for (int row = 0; row < 2; ++row) {
                const int m = wm * 32 + i * 16 + row * 8 + g;
#pragma unroll
                for (int j = 0; j < 8; ++j) {
                    const int n = wn * 64 + j * 8 + 2 * t4;
                    const float v0 = fmaxf(acc[i][j][row * 2 + 0] + bias_s[n], 0.f);
                    const float v1 = fmaxf(acc[i][j][row * 2 + 1] + bias_s[n + 1], 0.f);
                    const __half2 hv = __floats2half2_rn(v0, v1);
                    const uint32_t addr = h2b + (uint32_t)(m * HROW + (n >> 3) * 16
                                                           + (n & 7) * 2);
                    asm volatile("st.shared.b32 [%0], %1;"
                                 :: "r"(addr), "r"(*(const uint32_t*)&hv)
                                 : "memory");
                }
            }
        }
        CP_WAIT0();
        __syncthreads();

        // heads GEMM: 64x64x256, warp tile 32(m) x 16(n)
        const int wm2 = wid & 1;
        const int wn2 = wid >> 1;
        float acc2[2][2][4];
#pragma unroll
        for (int i = 0; i < 2; ++i)
#pragma unroll
            for (int j = 0; j < 2; ++j)
#pragma unroll
                for (int k = 0; k < 4; ++k) acc2[i][j][k] = 0.0f;

        uint32_t hoffA[2], hoffB;
#pragma unroll
        for (int i = 0; i < 2; ++i) {
            const int m = wm2 * 32 + i * 16 + (q & 1) * 8 + r;
            hoffA[i] = (uint32_t)(m * HROW + (q >> 1) * 16);
        }
        {
            const int n = wn2 * 16 + (q >> 1) * 8 + r;
            hoffB = (uint32_t)(n * HROW + (q & 1) * 16);
        }

#pragma unroll
        for (int c = 0; c < 16; ++c) {          // 16 k16 chunks
            const uint32_t koff = (uint32_t)(c * 32);
            uint32_t af2[2][4], bf2[4];
#pragma unroll
            for (int i = 0; i < 2; ++i)
                ldsm4(af2[i], h2b + hoffA[i] + koff);
            ldsm4(bf2, whb + hoffB + koff);
#pragma unroll
            for (int i = 0; i < 2; ++i)
#pragma unroll
                for (int j = 0; j < 2; ++j)
                    mma16816(acc2[i][j], af2[i], &bf2[j * 2]);
        }

        // epilogue: bias + pairwise softmax + store
#pragma unroll
        for (int i = 0; i < 2; ++i) {
#pragma unroll
            for (int row = 0; row < 2; ++row) {
                const int m = wm2 * 32 + i * 16 + row * 8 + g;
                float* op = out + (posb + m) * 54;
#pragma unroll
                for (int j = 0; j < 2; ++j) {
                    const int n0 = wn2 * 16 + j * 8 + 2 * t4;
                    if (n0 < 54) {
                        float v0 = acc2[i][j][row * 2 + 0] + bh_s[n0];
                        float v1 = acc2[i][j][row * 2 + 1] + bh_s[n0 + 1];
                        const int a   = n0 / 6;
                        const int rem = n0 - 6 * a;
                        if (rem == 0) {
                            const float mx = fmaxf(v0, v1);
                            const float e0 = __expf(v0 - mx);
                            const float e1 = __expf(v1 - mx);
                            const float inv = 1.0f / (e0 + e1);
                            v0 = e0 * inv;
                            v1 = e1 * inv;
                        }
                        *(float2*)(op + n0) = make_float2(v0, v1);
                    }
                }
            }
        }
    }
}

// ---------------------------------------------------------------------------
// Static stream/event resources (host objects; created once at load).
// ---------------------------------------------------------------------------
namespace {
struct OverlapRes {
    cudaStream_t sB = nullptr;
    cudaEvent_t  ev_fork = nullptr;
    cudaEvent_t  ev_join = nullptr;
    OverlapRes() {
        cudaStreamCreateWithFlags(&sB, cudaStreamNonBlocking);
        cudaEventCreateWithFlags(&ev_fork, cudaEventDisableTiming);
        cudaEventCreateWithFlags(&ev_join, cudaEventDisableTiming);
    }
};
OverlapRes g_ov;
}

// ---------------------------------------------------------------------------
extern "C" void kernel_launch(void* const* d_in, const int* in_sizes, int n_in,
                              void* d_out, int out_size)
{
    const float* x  = (const float*)d_in[0];
    const float* W1 = (const float*)d_in[1];
    const float* b1 = (const float*)d_in[2];
    const float* W2 = (const float*)d_in[3];
    const float* b2 = (const float*)d_in[4];
    const float* Wr = (const float*)d_in[5];
    const float* br = (const float*)d_in[6];
    const float* Wc = (const float*)d_in[7];
    const float* bc = (const float*)d_in[8];
    float* out = (float*)d_out;

    __half *x16p, *h1p, *w1tp, *w2tp, *whp;
    float *bhp;
    cudaGetSymbolAddress((void**)&x16p, g_x16);
    cudaGetSymbolAddress((void**)&h1p,  g_h1);
    cudaGetSymbolAddress((void**)&w1tp, g_w1t);
    cudaGetSymbolAddress((void**)&w2tp, g_w2t);
    cudaGetSymbolAddress((void**)&whp,  g_wh);
    cudaGetSymbolAddress((void**)&bhp,  g_bh);

    const int conv_smem = 5 * 20480 + 1536;   // 103936 B (2 CTAs/SM)
    cudaFuncSetAttribute(conv_mma<512, false>,
                         cudaFuncAttributeMaxDynamicSharedMemorySize, conv_smem);
    cudaFuncSetAttribute(conv_mma<256, true>,
                         cudaFuncAttributeMaxDynamicSharedMemorySize, conv_smem);

    prep_kernel<<<PREP_GRID, 256>>>(x, W1, W2, Wr, br, Wc, bc,
                                    x16p, w1tp, w2tp, whp, bhp);
    cudaEventRecord(g_ov.ev_fork, 0);
    cudaStreamWaitEvent(g_ov.sB, g_ov.ev_fork, 0);

    // Pair 0 (images 0-1, tiles [0,512)) on the main stream; pair 1
    // (images 2-3, tiles [512,1024)) on stream B. Stream order within each
    // pair is exactly the conv1->conv2 dependency; the pairs themselves
    // overlap freely on the GPU.
    conv_mma<512, false><<<512, 256, conv_smem>>>(
        x16p, w1tp, b1, h1p, nullptr, bhp, 0);
    conv_mma<512, false><<<512, 256, conv_smem, g_ov.sB>>>(
        x16p, w1tp, b1, h1p, nullptr, bhp, 512);
    conv_mma<256, true><<<512, 256, conv_smem>>>(
        h1p, w2tp, b2, out, whp, bhp, 0);
    conv_mma<256, true><<<512, 256, conv_smem, g_ov.sB>>>(
        h1p, w2tp, b2, out, whp, bhp, 512);

    cudaEventRecord(g_ov.ev_join, g_ov.sB);
    cudaStreamWaitEvent(0, g_ov.ev_join, 0);
}